// round 11
// baseline (speedup 1.0000x reference)
#include <cuda_runtime.h>
#include <cuda_bf16.h>
#include <cstdint>

// Problem constants (shapes fixed by the dataset; N/E derived at runtime from in_sizes)
#define MAXN 100000
#define CIN  256
#define COUT 64
#define CAP  192     // per-node adjacency bucket capacity (deg ~ Poisson(32); 17+ sigma)

// Scratch (device globals: no allocation allowed in kernel_launch).
__device__ int    g_deg[MAXN];                        // degree / bucket cursor
__device__ float  g_dinv[MAXN];
__device__ float4 g_hs [(size_t)MAXN * (COUT / 4)];   // h = x @ W, then scaled by dinv
__device__ int    g_csr[(size_t)MAXN * CAP];          // bucketed CSR: src ids per dst

// ---------------------------------------------------------------------------
// K0: zero bucket cursors
// ---------------------------------------------------------------------------
__global__ void zero_deg_kernel(int N) {
    int i = blockIdx.x * blockDim.x + threadIdx.x;
    if (i < N) g_deg[i] = 0;
}

// ---------------------------------------------------------------------------
// K1 (fused): blocks [0, gemmBlocks) run the tf32 GEMM writing RAW h;
//             blocks [gemmBlocks, ...) run the bucketed CSR fill.
// The two halves are data-independent, so the GPU overlaps the DRAM-bound
// GEMM with the atomic-bound CSR build inside one launch.
//
// GEMM: 256 threads = 8 warps; block tile 128x64; warp tile 32x32 (m16n8k8).
// Register double-buffering: phase p+1's x/W tiles are LDG'd into registers
// while phase p's MMAs consume smem. Conflict-free strides SKX=36 / SNW=72.
// ---------------------------------------------------------------------------
#define SKX 36
#define SNW 72

__device__ __forceinline__ uint32_t f2tf32(float f) {
    uint32_t r;
    asm("cvt.rna.tf32.f32 %0, %1;" : "=r"(r) : "f"(f));
    return r;
}

__global__ __launch_bounds__(256) void fused_gemm_csr_kernel(
    const float* __restrict__ x, const float* __restrict__ W,
    const int* __restrict__ ei, int N, int E, int gemmBlocks)
{
    __shared__ uint32_t xs[128 * SKX];
    __shared__ uint32_t ws[32 * SNW];

    if ((int)blockIdx.x >= gemmBlocks) {
        // ---------------- CSR fill part ----------------
        const int e = (blockIdx.x - gemmBlocks) * 256 + threadIdx.x;
        if (e < E) {
            const int s = __ldg(&ei[e]);
            const int d = __ldg(&ei[(size_t)E + e]);
            const int pos = atomicAdd(&g_deg[d], 1);
            if (pos < CAP) g_csr[d * CAP + pos] = s;
        }
        return;
    }

    // ---------------- GEMM part ----------------
    const int tid  = threadIdx.x;
    const int wid  = tid >> 5;
    const int lane = tid & 31;
    const int wm   = wid >> 1;
    const int wn   = wid & 1;
    const int gid  = lane >> 2;
    const int tig  = lane & 3;

    const int rowBase = blockIdx.x * 128;

    float c[2][4][4];
#pragma unroll
    for (int mt = 0; mt < 2; mt++)
#pragma unroll
        for (int nt = 0; nt < 4; nt++)
#pragma unroll
            for (int r = 0; r < 4; r++) c[mt][nt][r] = 0.f;

    const float4* x4 = reinterpret_cast<const float4*>(x);
    const float4* W4 = reinterpret_cast<const float4*>(W);

    // per-thread staging coordinates (constant across phases)
    int xrow[4], xkq[4];
#pragma unroll
    for (int i = 0; i < 4; ++i) {
        const int f = tid + 256 * i;
        xrow[i] = f >> 3;
        xkq[i]  = f & 7;
    }
    int wk[2], wnq[2];
#pragma unroll
    for (int i = 0; i < 2; ++i) {
        const int f = tid + 256 * i;
        wk[i]  = f >> 4;
        wnq[i] = f & 15;
    }

    float4 xr[4], wr[2];
    // prologue: load phase 0 into registers
#pragma unroll
    for (int i = 0; i < 4; ++i) {
        const int r = rowBase + xrow[i];
        xr[i] = (r < N) ? x4[(size_t)r * (CIN / 4) + 0 * 8 + xkq[i]]
                        : make_float4(0.f, 0.f, 0.f, 0.f);
    }
#pragma unroll
    for (int i = 0; i < 2; ++i)
        wr[i] = W4[(size_t)(0 * 32 + wk[i]) * (COUT / 4) + wnq[i]];

    for (int ph = 0; ph < 8; ++ph) {
        __syncthreads();
        // store current phase registers -> smem (with tf32 convert)
#pragma unroll
        for (int i = 0; i < 4; ++i) {
            uint4 t;
            t.x = f2tf32(xr[i].x); t.y = f2tf32(xr[i].y);
            t.z = f2tf32(xr[i].z); t.w = f2tf32(xr[i].w);
            *reinterpret_cast<uint4*>(&xs[xrow[i] * SKX + xkq[i] * 4]) = t;
        }
#pragma unroll
        for (int i = 0; i < 2; ++i) {
            uint4 t;
            t.x = f2tf32(wr[i].x); t.y = f2tf32(wr[i].y);
            t.z = f2tf32(wr[i].z); t.w = f2tf32(wr[i].w);
            *reinterpret_cast<uint4*>(&ws[wk[i] * SNW + wnq[i] * 4]) = t;
        }
        __syncthreads();

        // prefetch next phase into registers (LDGs overlap the MMAs below)
        if (ph + 1 < 8) {
#pragma unroll
            for (int i = 0; i < 4; ++i) {
                const int r = rowBase + xrow[i];
                xr[i] = (r < N) ? x4[(size_t)r * (CIN / 4) + (ph + 1) * 8 + xkq[i]]
                                : make_float4(0.f, 0.f, 0.f, 0.f);
            }
#pragma unroll
            for (int i = 0; i < 2; ++i)
                wr[i] = W4[(size_t)((ph + 1) * 32 + wk[i]) * (COUT / 4) + wnq[i]];
        }

        // ---- mma over 4 k8-steps ----
#pragma unroll
        for (int k8 = 0; k8 < 4; ++k8) {
            const int k0 = k8 * 8;
            uint32_t a[2][4], b[4][2];
#pragma unroll
            for (int mt = 0; mt < 2; ++mt) {
                const int m0 = wm * 32 + mt * 16;
                a[mt][0] = xs[(m0 + gid    ) * SKX + k0 + tig    ];
                a[mt][1] = xs[(m0 + 8 + gid) * SKX + k0 + tig    ];
                a[mt][2] = xs[(m0 + gid    ) * SKX + k0 + 4 + tig];
                a[mt][3] = xs[(m0 + 8 + gid) * SKX + k0 + 4 + tig];
            }
#pragma unroll
            for (int nt = 0; nt < 4; ++nt) {
                const int n0 = wn * 32 + nt * 8;
                b[nt][0] = ws[(k0 + tig    ) * SNW + n0 + gid];
                b[nt][1] = ws[(k0 + 4 + tig) * SNW + n0 + gid];
            }
#pragma unroll
            for (int mt = 0; mt < 2; ++mt)
#pragma unroll
                for (int nt = 0; nt < 4; ++nt) {
                    asm volatile(
                        "mma.sync.aligned.m16n8k8.row.col.f32.tf32.tf32.f32 "
                        "{%0,%1,%2,%3}, {%4,%5,%6,%7}, {%8,%9}, {%0,%1,%2,%3};"
                        : "+f"(c[mt][nt][0]), "+f"(c[mt][nt][1]),
                          "+f"(c[mt][nt][2]), "+f"(c[mt][nt][3])
                        : "r"(a[mt][0]), "r"(a[mt][1]),
                          "r"(a[mt][2]), "r"(a[mt][3]),
                          "r"(b[nt][0]), "r"(b[nt][1]));
                }
        }
    }

    // epilogue: store RAW h (dinv applied later by dinv_scale_kernel)
    float2* hs2 = reinterpret_cast<float2*>(g_hs);
#pragma unroll
    for (int mt = 0; mt < 2; ++mt) {
        const int r0 = rowBase + wm * 32 + mt * 16 + gid;
        const int r1 = r0 + 8;
#pragma unroll
        for (int nt = 0; nt < 4; ++nt) {
            const int cpair = wn * 16 + nt * 4 + tig;
            if (r0 < N)
                hs2[(size_t)r0 * (COUT / 2) + cpair] =
                    make_float2(c[mt][nt][0], c[mt][nt][1]);
            if (r1 < N)
                hs2[(size_t)r1 * (COUT / 2) + cpair] =
                    make_float2(c[mt][nt][2], c[mt][nt][3]);
        }
    }
}

// ---------------------------------------------------------------------------
// K2: dinv = rsqrt(deg+1); hs[row] *= dinv  (16 lanes per node, 1 float4 each)
// ---------------------------------------------------------------------------
__global__ __launch_bounds__(256) void dinv_scale_kernel(int N) {
    const int t    = blockIdx.x * blockDim.x + threadIdx.x;
    const int node = t >> 4;
    if (node >= N) return;
    const int c = t & 15;

    const float dv = rsqrtf((float)(g_deg[node] + 1));
    if (c == 0) g_dinv[node] = dv;

    float4 h = g_hs[(size_t)node * (COUT / 4) + c];
    h.x *= dv; h.y *= dv; h.z *= dv; h.w *= dv;
    g_hs[(size_t)node * (COUT / 4) + c] = h;
}

// ---------------------------------------------------------------------------
// K3: gather + finalize (atomic-free).
// 16 lanes per node, one float4 column chunk each. Register accumulation over
// the node's bucket; src ids broadcast via width-16 shuffles. Single store:
//   out[r][c] = dinv[r] * (sum_src hs[src][c] + hs[r][c]) + b[c]
// ---------------------------------------------------------------------------
__global__ __launch_bounds__(256) void gather_finalize_kernel(
    const float* __restrict__ b, float* __restrict__ out, int N)
{
    const int t    = blockIdx.x * blockDim.x + threadIdx.x;
    const int node = t >> 4;
    if (node >= N) return;
    const int c = threadIdx.x & 15;
    const unsigned gmask = 0xFFFFu << (threadIdx.x & 16);   // this half-warp

    const int   deg = min(g_deg[node], CAP);
    const float dv  = g_dinv[node];

    // self-loop term: dinv[r]^2 * h[r] after the final dv multiply
    float4 acc = __ldg(&g_hs[(size_t)node * (COUT / 4) + c]);

    const int base = node * CAP;
    int j0 = 0;
    for (; j0 + 16 <= deg; j0 += 16) {
        const int sv = __ldg(&g_csr[base + j0 + c]);
#pragma unroll
        for (int i = 0; i < 16; ++i) {
            const int s = __shfl_sync(gmask, sv, i, 16);
            const float4 v = __ldg(&g_hs[(size_t)s * (COUT / 4) + c]);
            acc.x += v.x; acc.y += v.y; acc.z += v.z; acc.w += v.w;
        }
    }
    if (j0 < deg) {
        const int myj = j0 + c;
        const int sv  = (myj < deg) ? __ldg(&g_csr[base + myj]) : 0;
        const int cnt = deg - j0;
        for (int i = 0; i < cnt; ++i) {
            const int s = __shfl_sync(gmask, sv, i, 16);
            const float4 v = __ldg(&g_hs[(size_t)s * (COUT / 4) + c]);
            acc.x += v.x; acc.y += v.y; acc.z += v.z; acc.w += v.w;
        }
    }

    const float4 bb = __ldg(&reinterpret_cast<const float4*>(b)[c]);
    reinterpret_cast<float4*>(out)[(size_t)node * (COUT / 4) + c] =
        make_float4(dv * acc.x + bb.x, dv * acc.y + bb.y,
                    dv * acc.z + bb.z, dv * acc.w + bb.w);
}

// ---------------------------------------------------------------------------
// Launch
// ---------------------------------------------------------------------------
extern "C" void kernel_launch(void* const* d_in, const int* in_sizes, int n_in,
                              void* d_out, int out_size) {
    const float* x  = (const float*)d_in[0];
    const int*   ei = (const int*)d_in[1];     // edge_index is int32 (JAX x64 off)
    const float* W  = (const float*)d_in[2];
    const float* b  = (const float*)d_in[3];
    float*       out = (float*)d_out;

    const int N = in_sizes[0] / CIN;
    const int E = in_sizes[1] / 2;

    const int gemmBlocks = (N + 127) / 128;
    const int csrBlocks  = (E + 255) / 256;

    zero_deg_kernel<<<(N + 255) / 256, 256>>>(N);
    fused_gemm_csr_kernel<<<gemmBlocks + csrBlocks, 256>>>(x, W, ei, N, E, gemmBlocks);
    dinv_scale_kernel<<<(N * 16 + 255) / 256, 256>>>(N);
    gather_finalize_kernel<<<(N * 16 + 255) / 256, 256>>>(b, out, N);
}

// round 12
// speedup vs baseline: 1.1047x; 1.1047x over previous
#include <cuda_runtime.h>
#include <cuda_bf16.h>
#include <cstdint>

// Problem constants (shapes fixed by the dataset; N/E derived at runtime from in_sizes)
#define MAXN 100000
#define CIN  256
#define COUT 64
#define CAP  192     // per-node adjacency bucket capacity (deg ~ Poisson(32); 17+ sigma)

// Scratch (device globals: no allocation allowed in kernel_launch).
__device__ int    g_deg[MAXN];                        // degree / bucket cursor
__device__ float  g_dinv[MAXN];
__device__ float4 g_hs [(size_t)MAXN * (COUT / 4)];   // h = x @ W, then scaled by dinv
__device__ int    g_csr[(size_t)MAXN * CAP];          // bucketed CSR: src ids per dst

// ---------------------------------------------------------------------------
// K0: zero bucket cursors
// ---------------------------------------------------------------------------
__global__ void zero_deg_kernel(int N) {
    int i = blockIdx.x * blockDim.x + threadIdx.x;
    if (i < N) g_deg[i] = 0;
}

// ---------------------------------------------------------------------------
// K1: bucketed CSR fill (also produces in-degree). edge_index is INT32.
// ---------------------------------------------------------------------------
__global__ __launch_bounds__(256) void csr_fill_kernel(const int* __restrict__ ei, int E) {
    int e = blockIdx.x * blockDim.x + threadIdx.x;
    if (e < E) {
        const int s = __ldg(&ei[e]);
        const int d = __ldg(&ei[(size_t)E + e]);
        const int pos = atomicAdd(&g_deg[d], 1);
        if (pos < CAP) g_csr[d * CAP + pos] = s;
    }
}

// ---------------------------------------------------------------------------
// K2: tf32 tensor-core GEMM  h[r][c] = sum_k x[r][k] * W[k][c]   (RAW h)
// 256 threads = 8 warps; block tile 128x64; warp tile 32x32 (m16n8k8).
// Register double-buffering: phase p+1's x/W tiles are LDG'd into registers
// while phase p's MMAs consume smem. Conflict-free strides SKX=36 / SNW=72.
// ---------------------------------------------------------------------------
#define SKX 36
#define SNW 72

__device__ __forceinline__ uint32_t f2tf32(float f) {
    uint32_t r;
    asm("cvt.rna.tf32.f32 %0, %1;" : "=r"(r) : "f"(f));
    return r;
}

__global__ __launch_bounds__(256) void gemm_tf32_kernel(
    const float* __restrict__ x, const float* __restrict__ W, int N)
{
    __shared__ uint32_t xs[128 * SKX];
    __shared__ uint32_t ws[32 * SNW];

    const int tid  = threadIdx.x;
    const int wid  = tid >> 5;
    const int lane = tid & 31;
    const int wm   = wid >> 1;
    const int wn   = wid & 1;
    const int gid  = lane >> 2;
    const int tig  = lane & 3;

    const int rowBase = blockIdx.x * 128;

    float c[2][4][4];
#pragma unroll
    for (int mt = 0; mt < 2; mt++)
#pragma unroll
        for (int nt = 0; nt < 4; nt++)
#pragma unroll
            for (int r = 0; r < 4; r++) c[mt][nt][r] = 0.f;

    const float4* x4 = reinterpret_cast<const float4*>(x);
    const float4* W4 = reinterpret_cast<const float4*>(W);

    // per-thread staging coordinates (constant across phases)
    int xrow[4], xkq[4];
#pragma unroll
    for (int i = 0; i < 4; ++i) {
        const int f = tid + 256 * i;
        xrow[i] = f >> 3;
        xkq[i]  = f & 7;
    }
    int wk[2], wnq[2];
#pragma unroll
    for (int i = 0; i < 2; ++i) {
        const int f = tid + 256 * i;
        wk[i]  = f >> 4;
        wnq[i] = f & 15;
    }

    float4 xr[4], wr[2];
    // prologue: load phase 0 into registers
#pragma unroll
    for (int i = 0; i < 4; ++i) {
        const int r = rowBase + xrow[i];
        xr[i] = (r < N) ? x4[(size_t)r * (CIN / 4) + xkq[i]]
                        : make_float4(0.f, 0.f, 0.f, 0.f);
    }
#pragma unroll
    for (int i = 0; i < 2; ++i)
        wr[i] = W4[(size_t)wk[i] * (COUT / 4) + wnq[i]];

    for (int ph = 0; ph < 8; ++ph) {
        __syncthreads();
        // store current phase registers -> smem (with tf32 convert)
#pragma unroll
        for (int i = 0; i < 4; ++i) {
            uint4 t;
            t.x = f2tf32(xr[i].x); t.y = f2tf32(xr[i].y);
            t.z = f2tf32(xr[i].z); t.w = f2tf32(xr[i].w);
            *reinterpret_cast<uint4*>(&xs[xrow[i] * SKX + xkq[i] * 4]) = t;
        }
#pragma unroll
        for (int i = 0; i < 2; ++i) {
            uint4 t;
            t.x = f2tf32(wr[i].x); t.y = f2tf32(wr[i].y);
            t.z = f2tf32(wr[i].z); t.w = f2tf32(wr[i].w);
            *reinterpret_cast<uint4*>(&ws[wk[i] * SNW + wnq[i] * 4]) = t;
        }
        __syncthreads();

        // prefetch next phase into registers (LDGs overlap the MMAs below)
        if (ph + 1 < 8) {
#pragma unroll
            for (int i = 0; i < 4; ++i) {
                const int r = rowBase + xrow[i];
                xr[i] = (r < N) ? x4[(size_t)r * (CIN / 4) + (ph + 1) * 8 + xkq[i]]
                                : make_float4(0.f, 0.f, 0.f, 0.f);
            }
#pragma unroll
            for (int i = 0; i < 2; ++i)
                wr[i] = W4[(size_t)((ph + 1) * 32 + wk[i]) * (COUT / 4) + wnq[i]];
        }

        // ---- mma over 4 k8-steps ----
#pragma unroll
        for (int k8 = 0; k8 < 4; ++k8) {
            const int k0 = k8 * 8;
            uint32_t a[2][4], b[4][2];
#pragma unroll
            for (int mt = 0; mt < 2; ++mt) {
                const int m0 = wm * 32 + mt * 16;
                a[mt][0] = xs[(m0 + gid    ) * SKX + k0 + tig    ];
                a[mt][1] = xs[(m0 + 8 + gid) * SKX + k0 + tig    ];
                a[mt][2] = xs[(m0 + gid    ) * SKX + k0 + 4 + tig];
                a[mt][3] = xs[(m0 + 8 + gid) * SKX + k0 + 4 + tig];
            }
#pragma unroll
            for (int nt = 0; nt < 4; ++nt) {
                const int n0 = wn * 32 + nt * 8;
                b[nt][0] = ws[(k0 + tig    ) * SNW + n0 + gid];
                b[nt][1] = ws[(k0 + 4 + tig) * SNW + n0 + gid];
            }
#pragma unroll
            for (int mt = 0; mt < 2; ++mt)
#pragma unroll
                for (int nt = 0; nt < 4; ++nt) {
                    asm volatile(
                        "mma.sync.aligned.m16n8k8.row.col.f32.tf32.tf32.f32 "
                        "{%0,%1,%2,%3}, {%4,%5,%6,%7}, {%8,%9}, {%0,%1,%2,%3};"
                        : "+f"(c[mt][nt][0]), "+f"(c[mt][nt][1]),
                          "+f"(c[mt][nt][2]), "+f"(c[mt][nt][3])
                        : "r"(a[mt][0]), "r"(a[mt][1]),
                          "r"(a[mt][2]), "r"(a[mt][3]),
                          "r"(b[nt][0]), "r"(b[nt][1]));
                }
        }
    }

    // epilogue: store RAW h (dinv applied by dinv_scale_kernel)
    float2* hs2 = reinterpret_cast<float2*>(g_hs);
#pragma unroll
    for (int mt = 0; mt < 2; ++mt) {
        const int r0 = rowBase + wm * 32 + mt * 16 + gid;
        const int r1 = r0 + 8;
#pragma unroll
        for (int nt = 0; nt < 4; ++nt) {
            const int cpair = wn * 16 + nt * 4 + tig;
            if (r0 < N)
                hs2[(size_t)r0 * (COUT / 2) + cpair] =
                    make_float2(c[mt][nt][0], c[mt][nt][1]);
            if (r1 < N)
                hs2[(size_t)r1 * (COUT / 2) + cpair] =
                    make_float2(c[mt][nt][2], c[mt][nt][3]);
        }
    }
}

// ---------------------------------------------------------------------------
// K3: dinv = rsqrt(deg+1); hs[row] *= dinv  (16 lanes per node, 1 float4 each)
// ---------------------------------------------------------------------------
__global__ __launch_bounds__(256) void dinv_scale_kernel(int N) {
    const int t    = blockIdx.x * blockDim.x + threadIdx.x;
    const int node = t >> 4;
    if (node >= N) return;
    const int c = t & 15;

    const float dv = rsqrtf((float)(g_deg[node] + 1));
    if (c == 0) g_dinv[node] = dv;

    float4 h = g_hs[(size_t)node * (COUT / 4) + c];
    h.x *= dv; h.y *= dv; h.z *= dv; h.w *= dv;
    g_hs[(size_t)node * (COUT / 4) + c] = h;
}

// ---------------------------------------------------------------------------
// K4: gather + finalize (atomic-free).
// 8 lanes per node, TWO float4 column chunks per lane (higher MLP per thread:
// each 8-edge chunk issues 16 independent LDG.128). Src ids broadcast via
// width-8 shuffles. Single store:
//   out[r][c] = dinv[r] * (sum_src hs[src][c] + hs[r][c]) + b[c]
// ---------------------------------------------------------------------------
__global__ __launch_bounds__(256) void gather_finalize_kernel(
    const float* __restrict__ b, float* __restrict__ out, int N)
{
    const int t    = blockIdx.x * blockDim.x + threadIdx.x;
    const int node = t >> 3;
    if (node >= N) return;
    const int c2 = threadIdx.x & 7;              // lane within node group
    const int c0 = c2 * 2;                       // first float4 index (0..14)
    const unsigned gmask = 0xFFu << (threadIdx.x & 24);   // this 8-lane group

    const int   deg = min(g_deg[node], CAP);
    const float dv  = g_dinv[node];

    // self-loop term: dinv[r]^2 * h[r] after the final dv multiply
    float4 acc0 = __ldg(&g_hs[(size_t)node * (COUT / 4) + c0]);
    float4 acc1 = __ldg(&g_hs[(size_t)node * (COUT / 4) + c0 + 1]);

    const int base = node * CAP;
    int j0 = 0;
    for (; j0 + 8 <= deg; j0 += 8) {
        const int sv = __ldg(&g_csr[base + j0 + c2]);
#pragma unroll
        for (int i = 0; i < 8; ++i) {
            const int s = __shfl_sync(gmask, sv, i, 8);
            const float4 v0 = __ldg(&g_hs[(size_t)s * (COUT / 4) + c0]);
            const float4 v1 = __ldg(&g_hs[(size_t)s * (COUT / 4) + c0 + 1]);
            acc0.x += v0.x; acc0.y += v0.y; acc0.z += v0.z; acc0.w += v0.w;
            acc1.x += v1.x; acc1.y += v1.y; acc1.z += v1.z; acc1.w += v1.w;
        }
    }
    if (j0 < deg) {
        const int myj = j0 + c2;
        const int sv  = (myj < deg) ? __ldg(&g_csr[base + myj]) : 0;
        const int cnt = deg - j0;
        for (int i = 0; i < cnt; ++i) {
            const int s = __shfl_sync(gmask, sv, i, 8);
            const float4 v0 = __ldg(&g_hs[(size_t)s * (COUT / 4) + c0]);
            const float4 v1 = __ldg(&g_hs[(size_t)s * (COUT / 4) + c0 + 1]);
            acc0.x += v0.x; acc0.y += v0.y; acc0.z += v0.z; acc0.w += v0.w;
            acc1.x += v1.x; acc1.y += v1.y; acc1.z += v1.z; acc1.w += v1.w;
        }
    }

    const float4* b4 = reinterpret_cast<const float4*>(b);
    const float4 bb0 = __ldg(&b4[c0]);
    const float4 bb1 = __ldg(&b4[c0 + 1]);
    float4* out4 = reinterpret_cast<float4*>(out);
    out4[(size_t)node * (COUT / 4) + c0] =
        make_float4(dv * acc0.x + bb0.x, dv * acc0.y + bb0.y,
                    dv * acc0.z + bb0.z, dv * acc0.w + bb0.w);
    out4[(size_t)node * (COUT / 4) + c0 + 1] =
        make_float4(dv * acc1.x + bb1.x, dv * acc1.y + bb1.y,
                    dv * acc1.z + bb1.z, dv * acc1.w + bb1.w);
}

// ---------------------------------------------------------------------------
// Launch
// ---------------------------------------------------------------------------
extern "C" void kernel_launch(void* const* d_in, const int* in_sizes, int n_in,
                              void* d_out, int out_size) {
    const float* x  = (const float*)d_in[0];
    const int*   ei = (const int*)d_in[1];     // edge_index is int32 (JAX x64 off)
    const float* W  = (const float*)d_in[2];
    const float* b  = (const float*)d_in[3];
    float*       out = (float*)d_out;

    const int N = in_sizes[0] / CIN;
    const int E = in_sizes[1] / 2;

    zero_deg_kernel<<<(N + 255) / 256, 256>>>(N);
    csr_fill_kernel<<<(E + 255) / 256, 256>>>(ei, E);
    gemm_tf32_kernel<<<(N + 127) / 128, 256>>>(x, W, N);
    dinv_scale_kernel<<<(N * 16 + 255) / 256, 256>>>(N);
    gather_finalize_kernel<<<(N * 8 + 255) / 256, 256>>>(b, out, N);
}

// round 13
// speedup vs baseline: 1.1196x; 1.0135x over previous
#include <cuda_runtime.h>
#include <cuda_bf16.h>
#include <cstdint>

// Problem constants (shapes fixed by the dataset; N/E derived at runtime from in_sizes)
#define MAXN 100000
#define CIN  256
#define COUT 64
#define CAP  192     // per-node adjacency bucket capacity (deg ~ Poisson(32); 17+ sigma)

// Scratch (device globals: no allocation allowed in kernel_launch).
__device__ int    g_deg[MAXN];                        // degree / bucket cursor
__device__ float  g_dinv[MAXN];
__device__ float4 g_hs [(size_t)MAXN * (COUT / 4)];   // hs = (x @ W) * dinv[row]
__device__ int    g_csr[(size_t)MAXN * CAP];          // bucketed CSR: src ids per dst

// ---------------------------------------------------------------------------
// K0: zero bucket cursors
// ---------------------------------------------------------------------------
__global__ void zero_deg_kernel(int N) {
    int i = blockIdx.x * blockDim.x + threadIdx.x;
    if (i < N) g_deg[i] = 0;
}

// ---------------------------------------------------------------------------
// K1: bucketed CSR fill (also produces in-degree). edge_index is INT32.
// ---------------------------------------------------------------------------
__global__ __launch_bounds__(256) void csr_fill_kernel(const int* __restrict__ ei, int E) {
    int e = blockIdx.x * blockDim.x + threadIdx.x;
    if (e < E) {
        const int s = __ldg(&ei[e]);
        const int d = __ldg(&ei[(size_t)E + e]);
        const int pos = atomicAdd(&g_deg[d], 1);
        if (pos < CAP) g_csr[d * CAP + pos] = s;
    }
}

// ---------------------------------------------------------------------------
// K2: dinv = rsqrt(deg + 1)   (+1 = self loop; always > 0). Tiny (N threads).
// ---------------------------------------------------------------------------
__global__ void dinv_kernel(int N) {
    int i = blockIdx.x * blockDim.x + threadIdx.x;
    if (i < N) g_dinv[i] = rsqrtf((float)(g_deg[i] + 1));
}

// ---------------------------------------------------------------------------
// K3: tf32 tensor-core GEMM  hs[r][c] = dinv[r] * sum_k x[r][k] * W[k][c]
// 256 threads = 8 warps; block tile 128x64; warp tile 32x32 (m16n8k8).
// Register double-buffering: phase p+1's x/W tiles are LDG'd into registers
// while phase p's MMAs consume smem. Conflict-free strides SKX=36 / SNW=72.
// dinv scale folded into the epilogue (free FMUL on registers).
// ---------------------------------------------------------------------------
#define SKX 36
#define SNW 72

__device__ __forceinline__ uint32_t f2tf32(float f) {
    uint32_t r;
    asm("cvt.rna.tf32.f32 %0, %1;" : "=r"(r) : "f"(f));
    return r;
}

__global__ __launch_bounds__(256) void gemm_tf32_kernel(
    const float* __restrict__ x, const float* __restrict__ W, int N)
{
    __shared__ uint32_t xs[128 * SKX];
    __shared__ uint32_t ws[32 * SNW];

    const int tid  = threadIdx.x;
    const int wid  = tid >> 5;
    const int lane = tid & 31;
    const int wm   = wid >> 1;
    const int wn   = wid & 1;
    const int gid  = lane >> 2;
    const int tig  = lane & 3;

    const int rowBase = blockIdx.x * 128;

    float c[2][4][4];
#pragma unroll
    for (int mt = 0; mt < 2; mt++)
#pragma unroll
        for (int nt = 0; nt < 4; nt++)
#pragma unroll
            for (int r = 0; r < 4; r++) c[mt][nt][r] = 0.f;

    const float4* x4 = reinterpret_cast<const float4*>(x);
    const float4* W4 = reinterpret_cast<const float4*>(W);

    // per-thread staging coordinates (constant across phases)
    int xrow[4], xkq[4];
#pragma unroll
    for (int i = 0; i < 4; ++i) {
        const int f = tid + 256 * i;
        xrow[i] = f >> 3;
        xkq[i]  = f & 7;
    }
    int wk[2], wnq[2];
#pragma unroll
    for (int i = 0; i < 2; ++i) {
        const int f = tid + 256 * i;
        wk[i]  = f >> 4;
        wnq[i] = f & 15;
    }

    float4 xr[4], wr[2];
    // prologue: load phase 0 into registers
#pragma unroll
    for (int i = 0; i < 4; ++i) {
        const int r = rowBase + xrow[i];
        xr[i] = (r < N) ? x4[(size_t)r * (CIN / 4) + xkq[i]]
                        : make_float4(0.f, 0.f, 0.f, 0.f);
    }
#pragma unroll
    for (int i = 0; i < 2; ++i)
        wr[i] = W4[(size_t)wk[i] * (COUT / 4) + wnq[i]];

    for (int ph = 0; ph < 8; ++ph) {
        __syncthreads();
        // store current phase registers -> smem (with tf32 convert)
#pragma unroll
        for (int i = 0; i < 4; ++i) {
            uint4 t;
            t.x = f2tf32(xr[i].x); t.y = f2tf32(xr[i].y);
            t.z = f2tf32(xr[i].z); t.w = f2tf32(xr[i].w);
            *reinterpret_cast<uint4*>(&xs[xrow[i] * SKX + xkq[i] * 4]) = t;
        }
#pragma unroll
        for (int i = 0; i < 2; ++i) {
            uint4 t;
            t.x = f2tf32(wr[i].x); t.y = f2tf32(wr[i].y);
            t.z = f2tf32(wr[i].z); t.w = f2tf32(wr[i].w);
            *reinterpret_cast<uint4*>(&ws[wk[i] * SNW + wnq[i] * 4]) = t;
        }
        __syncthreads();

        // prefetch next phase into registers (LDGs overlap the MMAs below)
        if (ph + 1 < 8) {
#pragma unroll
            for (int i = 0; i < 4; ++i) {
                const int r = rowBase + xrow[i];
                xr[i] = (r < N) ? x4[(size_t)r * (CIN / 4) + (ph + 1) * 8 + xkq[i]]
                                : make_float4(0.f, 0.f, 0.f, 0.f);
            }
#pragma unroll
            for (int i = 0; i < 2; ++i)
                wr[i] = W4[(size_t)((ph + 1) * 32 + wk[i]) * (COUT / 4) + wnq[i]];
        }

        // ---- mma over 4 k8-steps ----
#pragma unroll
        for (int k8 = 0; k8 < 4; ++k8) {
            const int k0 = k8 * 8;
            uint32_t a[2][4], b[4][2];
#pragma unroll
            for (int mt = 0; mt < 2; ++mt) {
                const int m0 = wm * 32 + mt * 16;
                a[mt][0] = xs[(m0 + gid    ) * SKX + k0 + tig    ];
                a[mt][1] = xs[(m0 + 8 + gid) * SKX + k0 + tig    ];
                a[mt][2] = xs[(m0 + gid    ) * SKX + k0 + 4 + tig];
                a[mt][3] = xs[(m0 + 8 + gid) * SKX + k0 + 4 + tig];
            }
#pragma unroll
            for (int nt = 0; nt < 4; ++nt) {
                const int n0 = wn * 32 + nt * 8;
                b[nt][0] = ws[(k0 + tig    ) * SNW + n0 + gid];
                b[nt][1] = ws[(k0 + 4 + tig) * SNW + n0 + gid];
            }
#pragma unroll
            for (int mt = 0; mt < 2; ++mt)
#pragma unroll
                for (int nt = 0; nt < 4; ++nt) {
                    asm volatile(
                        "mma.sync.aligned.m16n8k8.row.col.f32.tf32.tf32.f32 "
                        "{%0,%1,%2,%3}, {%4,%5,%6,%7}, {%8,%9}, {%0,%1,%2,%3};"
                        : "+f"(c[mt][nt][0]), "+f"(c[mt][nt][1]),
                          "+f"(c[mt][nt][2]), "+f"(c[mt][nt][3])
                        : "r"(a[mt][0]), "r"(a[mt][1]),
                          "r"(a[mt][2]), "r"(a[mt][3]),
                          "r"(b[nt][0]), "r"(b[nt][1]));
                }
        }
    }

    // ---- epilogue: scale by dinv (free on registers), store float2 pairs ----
    float2* hs2 = reinterpret_cast<float2*>(g_hs);
#pragma unroll
    for (int mt = 0; mt < 2; ++mt) {
        const int r0 = rowBase + wm * 32 + mt * 16 + gid;
        const int r1 = r0 + 8;
        const float dv0 = (r0 < N) ? g_dinv[r0] : 0.f;
        const float dv1 = (r1 < N) ? g_dinv[r1] : 0.f;
#pragma unroll
        for (int nt = 0; nt < 4; ++nt) {
            const int cpair = wn * 16 + nt * 4 + tig;
            if (r0 < N)
                hs2[(size_t)r0 * (COUT / 2) + cpair] =
                    make_float2(c[mt][nt][0] * dv0, c[mt][nt][1] * dv0);
            if (r1 < N)
                hs2[(size_t)r1 * (COUT / 2) + cpair] =
                    make_float2(c[mt][nt][2] * dv1, c[mt][nt][3] * dv1);
        }
    }
}

// ---------------------------------------------------------------------------
// K4: gather + finalize (atomic-free).
// 8 lanes per node, TWO float4 column chunks per lane (16 independent LDG.128
// per 8-edge chunk). Src ids broadcast via width-8 shuffles. Single store:
//   out[r][c] = dinv[r] * (sum_src hs[src][c] + hs[r][c]) + b[c]
// ---------------------------------------------------------------------------
__global__ __launch_bounds__(256) void gather_finalize_kernel(
    const float* __restrict__ b, float* __restrict__ out, int N)
{
    const int t    = blockIdx.x * blockDim.x + threadIdx.x;
    const int node = t >> 3;
    if (node >= N) return;
    const int c2 = threadIdx.x & 7;              // lane within node group
    const int c0 = c2 * 2;                       // first float4 index (0..14)
    const unsigned gmask = 0xFFu << (threadIdx.x & 24);   // this 8-lane group

    const int   deg = min(g_deg[node], CAP);
    const float dv  = g_dinv[node];

    // self-loop term: dinv[r]^2 * h[r] after the final dv multiply
    float4 acc0 = __ldg(&g_hs[(size_t)node * (COUT / 4) + c0]);
    float4 acc1 = __ldg(&g_hs[(size_t)node * (COUT / 4) + c0 + 1]);

    const int base = node * CAP;
    int j0 = 0;
    for (; j0 + 8 <= deg; j0 += 8) {
        const int sv = __ldg(&g_csr[base + j0 + c2]);
#pragma unroll
        for (int i = 0; i < 8; ++i) {
            const int s = __shfl_sync(gmask, sv, i, 8);
            const float4 v0 = __ldg(&g_hs[(size_t)s * (COUT / 4) + c0]);
            const float4 v1 = __ldg(&g_hs[(size_t)s * (COUT / 4) + c0 + 1]);
            acc0.x += v0.x; acc0.y += v0.y; acc0.z += v0.z; acc0.w += v0.w;
            acc1.x += v1.x; acc1.y += v1.y; acc1.z += v1.z; acc1.w += v1.w;
        }
    }
    if (j0 < deg) {
        const int myj = j0 + c2;
        const int sv  = (myj < deg) ? __ldg(&g_csr[base + myj]) : 0;
        const int cnt = deg - j0;
        for (int i = 0; i < cnt; ++i) {
            const int s = __shfl_sync(gmask, sv, i, 8);
            const float4 v0 = __ldg(&g_hs[(size_t)s * (COUT / 4) + c0]);
            const float4 v1 = __ldg(&g_hs[(size_t)s * (COUT / 4) + c0 + 1]);
            acc0.x += v0.x; acc0.y += v0.y; acc0.z += v0.z; acc0.w += v0.w;
            acc1.x += v1.x; acc1.y += v1.y; acc1.z += v1.z; acc1.w += v1.w;
        }
    }

    const float4* b4 = reinterpret_cast<const float4*>(b);
    const float4 bb0 = __ldg(&b4[c0]);
    const float4 bb1 = __ldg(&b4[c0 + 1]);
    float4* out4 = reinterpret_cast<float4*>(out);
    out4[(size_t)node * (COUT / 4) + c0] =
        make_float4(dv * acc0.x + bb0.x, dv * acc0.y + bb0.y,
                    dv * acc0.z + bb0.z, dv * acc0.w + bb0.w);
    out4[(size_t)node * (COUT / 4) + c0 + 1] =
        make_float4(dv * acc1.x + bb1.x, dv * acc1.y + bb1.y,
                    dv * acc1.z + bb1.z, dv * acc1.w + bb1.w);
}

// ---------------------------------------------------------------------------
// Launch
// ---------------------------------------------------------------------------
extern "C" void kernel_launch(void* const* d_in, const int* in_sizes, int n_in,
                              void* d_out, int out_size) {
    const float* x  = (const float*)d_in[0];
    const int*   ei = (const int*)d_in[1];     // edge_index is int32 (JAX x64 off)
    const float* W  = (const float*)d_in[2];
    const float* b  = (const float*)d_in[3];
    float*       out = (float*)d_out;

    const int N = in_sizes[0] / CIN;
    const int E = in_sizes[1] / 2;

    zero_deg_kernel<<<(N + 255) / 256, 256>>>(N);
    csr_fill_kernel<<<(E + 255) / 256, 256>>>(ei, E);
    dinv_kernel<<<(N + 255) / 256, 256>>>(N);
    gemm_tf32_kernel<<<(N + 127) / 128, 256>>>(x, W, N);
    gather_finalize_kernel<<<(N * 8 + 255) / 256, 256>>>(b, out, N);
}

// round 14
// speedup vs baseline: 1.2397x; 1.1072x over previous
#include <cuda_runtime.h>
#include <cuda_bf16.h>
#include <cstdint>

// Problem constants (shapes fixed by the dataset; N/E derived at runtime from in_sizes)
#define MAXN 100000
#define CIN  256
#define COUT 64
#define CAP  192     // per-node adjacency bucket capacity (deg ~ Poisson(32); 17+ sigma)

// Scratch (device globals: no allocation allowed in kernel_launch).
__device__ int    g_deg[MAXN];                        // degree / bucket cursor
__device__ float4 g_hs [(size_t)MAXN * (COUT / 4)];   // hs = (x @ W) * dinv[row]
__device__ int    g_csr[(size_t)MAXN * CAP];          // bucketed CSR: src ids per dst

// ---------------------------------------------------------------------------
// K0: zero bucket cursors
// ---------------------------------------------------------------------------
__global__ void zero_deg_kernel(int N) {
    int i = blockIdx.x * blockDim.x + threadIdx.x;
    if (i < N) g_deg[i] = 0;
}

// ---------------------------------------------------------------------------
// K1: bucketed CSR fill (also produces in-degree). edge_index is INT32.
// 4 edges per thread via int4 loads (E divisible by 4 handled with tail).
// ---------------------------------------------------------------------------
__global__ __launch_bounds__(256) void csr_fill_kernel(const int* __restrict__ ei, int E) {
    const int q  = blockIdx.x * blockDim.x + threadIdx.x;   // quad index
    const int E4 = E >> 2;
    if (q < E4) {
        const int4 s4 = __ldg(reinterpret_cast<const int4*>(ei) + q);
        const int4 d4 = __ldg(reinterpret_cast<const int4*>(ei + E) + q);
        int pos;
        pos = atomicAdd(&g_deg[d4.x], 1); if (pos < CAP) g_csr[d4.x * CAP + pos] = s4.x;
        pos = atomicAdd(&g_deg[d4.y], 1); if (pos < CAP) g_csr[d4.y * CAP + pos] = s4.y;
        pos = atomicAdd(&g_deg[d4.z], 1); if (pos < CAP) g_csr[d4.z * CAP + pos] = s4.z;
        pos = atomicAdd(&g_deg[d4.w], 1); if (pos < CAP) g_csr[d4.w * CAP + pos] = s4.w;
    } else if (q == E4) {
        // tail (E % 4 edges)
        for (int e = E4 * 4; e < E; ++e) {
            const int s = __ldg(&ei[e]);
            const int d = __ldg(&ei[(size_t)E + e]);
            const int pos = atomicAdd(&g_deg[d], 1);
            if (pos < CAP) g_csr[d * CAP + pos] = s;
        }
    }
}

// ---------------------------------------------------------------------------
// K2: tf32 tensor-core GEMM  hs[r][c] = rsqrt(deg[r]+1) * sum_k x[r][k]*W[k][c]
// 256 threads = 8 warps; block tile 128x64; warp tile 32x32 (m16n8k8).
// Register double-buffering: phase p+1's x/W tiles are LDG'd into registers
// while phase p's MMAs consume smem. Conflict-free strides SKX=36 / SNW=72.
// dinv computed on the fly from g_deg (MUFU) and folded into the epilogue.
// ---------------------------------------------------------------------------
#define SKX 36
#define SNW 72

__device__ __forceinline__ uint32_t f2tf32(float f) {
    uint32_t r;
    asm("cvt.rna.tf32.f32 %0, %1;" : "=r"(r) : "f"(f));
    return r;
}

__global__ __launch_bounds__(256) void gemm_tf32_kernel(
    const float* __restrict__ x, const float* __restrict__ W, int N)
{
    __shared__ uint32_t xs[128 * SKX];
    __shared__ uint32_t ws[32 * SNW];

    const int tid  = threadIdx.x;
    const int wid  = tid >> 5;
    const int lane = tid & 31;
    const int wm   = wid >> 1;
    const int wn   = wid & 1;
    const int gid  = lane >> 2;
    const int tig  = lane & 3;

    const int rowBase = blockIdx.x * 128;

    float c[2][4][4];
#pragma unroll
    for (int mt = 0; mt < 2; mt++)
#pragma unroll
        for (int nt = 0; nt < 4; nt++)
#pragma unroll
            for (int r = 0; r < 4; r++) c[mt][nt][r] = 0.f;

    const float4* x4 = reinterpret_cast<const float4*>(x);
    const float4* W4 = reinterpret_cast<const float4*>(W);

    // per-thread staging coordinates (constant across phases)
    int xrow[4], xkq[4];
#pragma unroll
    for (int i = 0; i < 4; ++i) {
        const int f = tid + 256 * i;
        xrow[i] = f >> 3;
        xkq[i]  = f & 7;
    }
    int wk[2], wnq[2];
#pragma unroll
    for (int i = 0; i < 2; ++i) {
        const int f = tid + 256 * i;
        wk[i]  = f >> 4;
        wnq[i] = f & 15;
    }

    float4 xr[4], wr[2];
    // prologue: load phase 0 into registers
#pragma unroll
    for (int i = 0; i < 4; ++i) {
        const int r = rowBase + xrow[i];
        xr[i] = (r < N) ? x4[(size_t)r * (CIN / 4) + xkq[i]]
                        : make_float4(0.f, 0.f, 0.f, 0.f);
    }
#pragma unroll
    for (int i = 0; i < 2; ++i)
        wr[i] = W4[(size_t)wk[i] * (COUT / 4) + wnq[i]];

    for (int ph = 0; ph < 8; ++ph) {
        __syncthreads();
        // store current phase registers -> smem (with tf32 convert)
#pragma unroll
        for (int i = 0; i < 4; ++i) {
            uint4 t;
            t.x = f2tf32(xr[i].x); t.y = f2tf32(xr[i].y);
            t.z = f2tf32(xr[i].z); t.w = f2tf32(xr[i].w);
            *reinterpret_cast<uint4*>(&xs[xrow[i] * SKX + xkq[i] * 4]) = t;
        }
#pragma unroll
        for (int i = 0; i < 2; ++i) {
            uint4 t;
            t.x = f2tf32(wr[i].x); t.y = f2tf32(wr[i].y);
            t.z = f2tf32(wr[i].z); t.w = f2tf32(wr[i].w);
            *reinterpret_cast<uint4*>(&ws[wk[i] * SNW + wnq[i] * 4]) = t;
        }
        __syncthreads();

        // prefetch next phase into registers (LDGs overlap the MMAs below)
        if (ph + 1 < 8) {
#pragma unroll
            for (int i = 0; i < 4; ++i) {
                const int r = rowBase + xrow[i];
                xr[i] = (r < N) ? x4[(size_t)r * (CIN / 4) + (ph + 1) * 8 + xkq[i]]
                                : make_float4(0.f, 0.f, 0.f, 0.f);
            }
#pragma unroll
            for (int i = 0; i < 2; ++i)
                wr[i] = W4[(size_t)((ph + 1) * 32 + wk[i]) * (COUT / 4) + wnq[i]];
        }

        // ---- mma over 4 k8-steps ----
#pragma unroll
        for (int k8 = 0; k8 < 4; ++k8) {
            const int k0 = k8 * 8;
            uint32_t a[2][4], b[4][2];
#pragma unroll
            for (int mt = 0; mt < 2; ++mt) {
                const int m0 = wm * 32 + mt * 16;
                a[mt][0] = xs[(m0 + gid    ) * SKX + k0 + tig    ];
                a[mt][1] = xs[(m0 + 8 + gid) * SKX + k0 + tig    ];
                a[mt][2] = xs[(m0 + gid    ) * SKX + k0 + 4 + tig];
                a[mt][3] = xs[(m0 + 8 + gid) * SKX + k0 + 4 + tig];
            }
#pragma unroll
            for (int nt = 0; nt < 4; ++nt) {
                const int n0 = wn * 32 + nt * 8;
                b[nt][0] = ws[(k0 + tig    ) * SNW + n0 + gid];
                b[nt][1] = ws[(k0 + 4 + tig) * SNW + n0 + gid];
            }
#pragma unroll
            for (int mt = 0; mt < 2; ++mt)
#pragma unroll
                for (int nt = 0; nt < 4; ++nt) {
                    asm volatile(
                        "mma.sync.aligned.m16n8k8.row.col.f32.tf32.tf32.f32 "
                        "{%0,%1,%2,%3}, {%4,%5,%6,%7}, {%8,%9}, {%0,%1,%2,%3};"
                        : "+f"(c[mt][nt][0]), "+f"(c[mt][nt][1]),
                          "+f"(c[mt][nt][2]), "+f"(c[mt][nt][3])
                        : "r"(a[mt][0]), "r"(a[mt][1]),
                          "r"(a[mt][2]), "r"(a[mt][3]),
                          "r"(b[nt][0]), "r"(b[nt][1]));
                }
        }
    }

    // ---- epilogue: dinv on the fly, scale, store float2 pairs ----
    float2* hs2 = reinterpret_cast<float2*>(g_hs);
#pragma unroll
    for (int mt = 0; mt < 2; ++mt) {
        const int r0 = rowBase + wm * 32 + mt * 16 + gid;
        const int r1 = r0 + 8;
        const float dv0 = (r0 < N) ? rsqrtf((float)(g_deg[r0] + 1)) : 0.f;
        const float dv1 = (r1 < N) ? rsqrtf((float)(g_deg[r1] + 1)) : 0.f;
#pragma unroll
        for (int nt = 0; nt < 4; ++nt) {
            const int cpair = wn * 16 + nt * 4 + tig;
            if (r0 < N)
                hs2[(size_t)r0 * (COUT / 2) + cpair] =
                    make_float2(c[mt][nt][0] * dv0, c[mt][nt][1] * dv0);
            if (r1 < N)
                hs2[(size_t)r1 * (COUT / 2) + cpair] =
                    make_float2(c[mt][nt][2] * dv1, c[mt][nt][3] * dv1);
        }
    }
}

// ---------------------------------------------------------------------------
// K3: gather + finalize (atomic-free).  [R9 16-lane form — proven fastest]
// 16 lanes per node, one float4 column chunk each. Register accumulation over
// the node's bucket; src ids broadcast via width-16 shuffles. Single store:
//   out[r][c] = dinv[r] * (sum_src hs[src][c] + hs[r][c]) + b[c]
// dinv computed on the fly from g_deg.
// ---------------------------------------------------------------------------
__global__ __launch_bounds__(256) void gather_finalize_kernel(
    const float* __restrict__ b, float* __restrict__ out, int N)
{
    const int t    = blockIdx.x * blockDim.x + threadIdx.x;
    const int node = t >> 4;
    if (node >= N) return;
    const int c = threadIdx.x & 15;
    const unsigned gmask = 0xFFFFu << (threadIdx.x & 16);   // this half-warp

    const int   degRaw = g_deg[node];
    const int   deg    = min(degRaw, CAP);
    const float dv     = rsqrtf((float)(degRaw + 1));

    // self-loop term: dinv[r]^2 * h[r] after the final dv multiply
    float4 acc = __ldg(&g_hs[(size_t)node * (COUT / 4) + c]);

    const int base = node * CAP;
    int j0 = 0;
    for (; j0 + 16 <= deg; j0 += 16) {
        const int sv = __ldg(&g_csr[base + j0 + c]);
#pragma unroll
        for (int i = 0; i < 16; ++i) {
            const int s = __shfl_sync(gmask, sv, i, 16);
            const float4 v = __ldg(&g_hs[(size_t)s * (COUT / 4) + c]);
            acc.x += v.x; acc.y += v.y; acc.z += v.z; acc.w += v.w;
        }
    }
    if (j0 < deg) {
        const int myj = j0 + c;
        const int sv  = (myj < deg) ? __ldg(&g_csr[base + myj]) : 0;
        const int cnt = deg - j0;
        for (int i = 0; i < cnt; ++i) {
            const int s = __shfl_sync(gmask, sv, i, 16);
            const float4 v = __ldg(&g_hs[(size_t)s * (COUT / 4) + c]);
            acc.x += v.x; acc.y += v.y; acc.z += v.z; acc.w += v.w;
        }
    }

    const float4 bb = __ldg(&reinterpret_cast<const float4*>(b)[c]);
    reinterpret_cast<float4*>(out)[(size_t)node * (COUT / 4) + c] =
        make_float4(dv * acc.x + bb.x, dv * acc.y + bb.y,
                    dv * acc.z + bb.z, dv * acc.w + bb.w);
}

// ---------------------------------------------------------------------------
// Launch
// ---------------------------------------------------------------------------
extern "C" void kernel_launch(void* const* d_in, const int* in_sizes, int n_in,
                              void* d_out, int out_size) {
    const float* x  = (const float*)d_in[0];
    const int*   ei = (const int*)d_in[1];     // edge_index is int32 (JAX x64 off)
    const float* W  = (const float*)d_in[2];
    const float* b  = (const float*)d_in[3];
    float*       out = (float*)d_out;

    const int N = in_sizes[0] / CIN;
    const int E = in_sizes[1] / 2;

    const int quads = (E >> 2) + 1;   // +1 block slot for the tail thread

    zero_deg_kernel<<<(N + 255) / 256, 256>>>(N);
    csr_fill_kernel<<<(quads + 255) / 256, 256>>>(ei, E);
    gemm_tf32_kernel<<<(N + 127) / 128, 256>>>(x, W, N);
    gather_finalize_kernel<<<(N * 16 + 255) / 256, 256>>>(b, out, N);
}